// round 6
// baseline (speedup 1.0000x reference)
#include <cuda_runtime.h>
#include <cstdint>

#define CC 256
#define BB 1024
typedef unsigned long long ull;

// Duplicated edge weights: g_W2[j*CC + c] = float2(w, w), w = w3[e(min(j,c),max(j,c))], diag 0.
// LDG.64 yields an aligned register pair -> zero packing MOVs in the hot loop.
__device__ float2 g_W2[CC * CC];

__global__ void build_W2_kernel(const float* __restrict__ w3) {
    int idx = blockIdx.x * blockDim.x + threadIdx.x;
    if (idx >= CC * CC) return;
    int j = idx >> 8;
    int c = idx & 255;
    float v = 0.0f;
    if (j != c) {
        int p = j < c ? j : c;
        int q = j < c ? c : j;
        int e = p * (2 * CC - p - 1) / 2 + (q - p - 1);  // np.triu_indices(CC,1)
        v = w3[e];
    }
    g_W2[idx] = make_float2(v, v);
}

// ---- packed f32x2 helpers (sm_100a) ----
__device__ __forceinline__ ull pk2(float lo, float hi) {
    ull r;
    asm("mov.b64 %0, {%1, %2};" : "=l"(r) : "f"(lo), "f"(hi));
    return r;
}
__device__ __forceinline__ void upk2(ull v, float& lo, float& hi) {
    asm("mov.b64 {%0, %1}, %2;" : "=f"(lo), "=f"(hi) : "l"(v));
}
__device__ __forceinline__ ull add2(ull a, ull b) {
    ull r;
    asm("add.rn.f32x2 %0, %1, %2;" : "=l"(r) : "l"(a), "l"(b));
    return r;
}
__device__ __forceinline__ ull mul2(ull a, ull b) {
    ull r;
    asm("mul.rn.f32x2 %0, %1, %2;" : "=l"(r) : "l"(a), "l"(b));
    return r;
}
__device__ __forceinline__ ull fma2_(ull a, ull b, ull c) {
    ull r;
    asm("fma.rn.f32x2 %0, %1, %2, %3;" : "=l"(r) : "l"(a), "l"(b), "l"(c));
    return r;
}

// out[b,c] = sum_j u * (x_j - x_c) * W[j,c]
// t' = 0.505*(w2[0] + a w2[1] + a^2 w2[2] + a^3 w2[3]),  a = |x_c - x_j|
// u  = t' + (0.495/0.505)*|t'|         (== leaky_relu factor, sign folded into d)
//
// grid = 512 blocks (one packed row-pair each), blockDim = 256 (channel c).
// Each thread sums all 256 j's as TWO independent 128-j streams (ILP 2, MLP 8).
__global__ __launch_bounds__(256, 4) void son_main_kernel(
    const float* __restrict__ x, const float* __restrict__ w1,
    const float* __restrict__ w2, float* __restrict__ out)
{
    __shared__ float2 xs[CC];        // xs[j] = (row r0, row r0+1) * w1[j]

    const int c = threadIdx.x;
    const int r0 = blockIdx.x * 2;

    const float w1j = w1[c];
    const float a0f = x[r0 * CC + c] * w1j;
    const float a1f = x[(r0 + 1) * CC + c] * w1j;
    xs[c] = make_float2(a0f, a1f);

    // -x_c (both rows) straight from registers — no smem round-trip needed
    const ull nxc = pk2(-a0f, -a1f);
    __syncthreads();

    // prescaled polynomial coefficients (x 0.505)
    const float s0 = 0.505f * w2[0], s1 = 0.505f * w2[1];
    const float s2 = 0.505f * w2[2], s3 = 0.505f * w2[3];
    const ull C0 = pk2(s0, s0), C1 = pk2(s1, s1);
    const ull C2 = pk2(s2, s2), C3 = pk2(s3, s3);
    const float kf = 0.495f / 0.505f;
    const ull K = pk2(kf, kf);

    const ull* wpA = reinterpret_cast<const ull*>(g_W2) + c;              // j stream
    const ull* wpB = reinterpret_cast<const ull*>(g_W2) + 128 * CC + c;   // j+128 stream
    const ull* xp  = reinterpret_cast<const ull*>(xs);

    ull accA = 0ULL, accB = 0ULL;
#pragma unroll 4
    for (int j = 0; j < 128; j++) {
        ull wA  = __ldg(wpA + j * CC);   // LDG.64, coalesced, 8 in flight at unroll 4
        ull wB  = __ldg(wpB + j * CC);
        ull xjA = xp[j];                 // LDS.64 broadcast (same addr across warp)
        ull xjB = xp[j + 128];
        // stream A
        ull dA = add2(xjA, nxc);
        ull aA = dA & 0x7fffffff7fffffffULL;
        ull tA = fma2_(C3, aA, C2);
        tA = fma2_(tA, aA, C1);
        tA = fma2_(tA, aA, C0);
        ull uA = fma2_(K, tA & 0x7fffffff7fffffffULL, tA);
        accA = fma2_(uA, mul2(dA, wA), accA);
        // stream B (independent chain -> ILP 2)
        ull dB = add2(xjB, nxc);
        ull aB = dB & 0x7fffffff7fffffffULL;
        ull tB = fma2_(C3, aB, C2);
        tB = fma2_(tB, aB, C1);
        tB = fma2_(tB, aB, C0);
        ull uB = fma2_(K, tB & 0x7fffffff7fffffffULL, tB);
        accB = fma2_(uB, mul2(dB, wB), accB);
    }

    ull acc = add2(accA, accB);
    float lo, hi;
    upk2(acc, lo, hi);
    out[r0 * CC + c]       = lo;
    out[(r0 + 1) * CC + c] = hi;
}

extern "C" void kernel_launch(void* const* d_in, const int* in_sizes, int n_in,
                              void* d_out, int out_size) {
    // Identify inputs by element count (robust to ordering):
    // x: 262144, w1: 256, w2: 4, w3: 32640, diff_indices: 8355840 (unused)
    const float* x = nullptr;
    const float* w1 = nullptr;
    const float* w2 = nullptr;
    const float* w3 = nullptr;
    for (int i = 0; i < n_in; i++) {
        switch (in_sizes[i]) {
            case BB * CC:            x  = (const float*)d_in[i]; break;
            case CC:                 w1 = (const float*)d_in[i]; break;
            case 4:                  w2 = (const float*)d_in[i]; break;
            case CC * (CC - 1) / 2:  w3 = (const float*)d_in[i]; break;
            default: break;  // diff_indices not needed
        }
    }

    build_W2_kernel<<<(CC * CC + 255) / 256, 256>>>(w3);
    son_main_kernel<<<BB / 2, 256>>>(x, w1, w2, (float*)d_out);
}

// round 7
// speedup vs baseline: 1.0135x; 1.0135x over previous
#include <cuda_runtime.h>
#include <cstdint>

#define CC 256
#define BB 1024
#define CTILE 32          // channels per block
#define PAIRS 8           // row-pairs per block (16 rows)
typedef unsigned long long ull;

// Scalar expanded symmetric edge weights: g_W[j*CC + c] = w3[e(min(j,c),max(j,c))], diag 0.
__device__ float g_W[CC * CC];

__global__ void build_W_kernel(const float* __restrict__ w3) {
    int idx = blockIdx.x * blockDim.x + threadIdx.x;
    if (idx >= CC * CC) return;
    int j = idx >> 8;
    int c = idx & 255;
    float v = 0.0f;
    if (j != c) {
        int p = j < c ? j : c;
        int q = j < c ? c : j;
        int e = p * (2 * CC - p - 1) / 2 + (q - p - 1);  // np.triu_indices(CC,1)
        v = w3[e];
    }
    g_W[idx] = v;
}

// ---- packed f32x2 helpers (sm_100a) ----
__device__ __forceinline__ ull pk2(float lo, float hi) {
    ull r;
    asm("mov.b64 %0, {%1, %2};" : "=l"(r) : "f"(lo), "f"(hi));
    return r;
}
__device__ __forceinline__ void upk2(ull v, float& lo, float& hi) {
    asm("mov.b64 {%0, %1}, %2;" : "=f"(lo), "=f"(hi) : "l"(v));
}
__device__ __forceinline__ ull add2(ull a, ull b) {
    ull r;
    asm("add.rn.f32x2 %0, %1, %2;" : "=l"(r) : "l"(a), "l"(b));
    return r;
}
__device__ __forceinline__ ull mul2(ull a, ull b) {
    ull r;
    asm("mul.rn.f32x2 %0, %1, %2;" : "=l"(r) : "l"(a), "l"(b));
    return r;
}
__device__ __forceinline__ ull fma2_(ull a, ull b, ull c) {
    ull r;
    asm("fma.rn.f32x2 %0, %1, %2, %3;" : "=l"(r) : "l"(a), "l"(b), "l"(c));
    return r;
}

// out[b,c] = sum_j u * (x_j - x_c) * W[j,c]
// t' = 0.505*(w2[0] + a w2[1] + a^2 w2[2] + a^3 w2[3]),  a = |x_c - x_j|
// u  = t' + (0.495/0.505)*|t'|        (== leaky_relu factor, sign folded into d)
//
// Block = (32 channels, 8 row-pairs) = 256 threads; W tile + x rows staged in smem.
// Hot loop has ZERO global loads: LDS.32 (W, conflict-free) + LDS.64 (xj, broadcast).
__global__ __launch_bounds__(256, 4) void son_main_kernel(
    const float* __restrict__ x, const float* __restrict__ w1,
    const float* __restrict__ w2, float* __restrict__ out)
{
    __shared__ float  Wt[CC][CTILE];     // 32 KB: W[j][c-tile]
    __shared__ float2 xs[PAIRS][CC];     // 16 KB: xs[p][j] = (row 2p, row 2p+1)*w1[j]

    const int tid = threadIdx.y * CTILE + threadIdx.x;   // 0..255
    const int c0  = blockIdx.x * CTILE;
    const int r0  = blockIdx.y * (2 * PAIRS);

    // Stage W tile: 2048 float4, 8 per thread, coalesced (one 128B j-row per warp step).
    {
        const float4* gw4 = reinterpret_cast<const float4*>(g_W + c0);  // row stride CC floats
#pragma unroll
        for (int k = 0; k < 8; k++) {
            int f4idx = tid + k * 256;          // 0..2047
            int j  = f4idx >> 3;                // /8 quads per row
            int qc = f4idx & 7;
            float4 v = __ldg(reinterpret_cast<const float4*>(g_W + j * CC + c0) + qc);
            *reinterpret_cast<float4*>(&Wt[j][qc * 4]) = v;
        }
        (void)gw4;
    }

    // Stage x rows: thread tid owns channel tid for all 8 pairs.
    {
        float w1s = w1[tid];
#pragma unroll
        for (int p = 0; p < PAIRS; p++) {
            float lo = x[(r0 + 2 * p) * CC + tid] * w1s;
            float hi = x[(r0 + 2 * p + 1) * CC + tid] * w1s;
            xs[p][tid] = make_float2(lo, hi);
        }
    }
    __syncthreads();

    // prescaled polynomial coefficients (x 0.505)
    const float s0 = 0.505f * w2[0], s1 = 0.505f * w2[1];
    const float s2 = 0.505f * w2[2], s3 = 0.505f * w2[3];
    const ull C0 = pk2(s0, s0), C1 = pk2(s1, s1);
    const ull C2 = pk2(s2, s2), C3 = pk2(s3, s3);
    const float kf = 0.495f / 0.505f;
    const ull K = pk2(kf, kf);

    const int cx = threadIdx.x;          // channel lane within tile
    const int p  = threadIdx.y;          // row-pair
    const int cg = c0 + cx;              // global channel

    // -x_c for both rows (sign-bit flip, alu pipe)
    const ull nxc = (*reinterpret_cast<const ull*>(&xs[p][cg])) ^ 0x8000000080000000ULL;

    const ull* xp = reinterpret_cast<const ull*>(&xs[p][0]);

    ull acc = 0ULL;
#pragma unroll 4
    for (int j = 0; j < CC; j++) {
        float w = Wt[j][cx];             // LDS.32, conflict-free (warp = 32 consecutive cx)
        ull wpk = pk2(w, w);
        ull xj  = xp[j];                 // LDS.64 broadcast (whole warp same addr)
        ull d = add2(xj, nxc);
        ull a = d & 0x7fffffff7fffffffULL;
        ull t = fma2_(C3, a, C2);
        t = fma2_(t, a, C1);
        t = fma2_(t, a, C0);
        ull u = fma2_(K, t & 0x7fffffff7fffffffULL, t);
        acc = fma2_(u, mul2(d, wpk), acc);
    }

    float lo, hi;
    upk2(acc, lo, hi);
    out[(r0 + 2 * p) * CC + cg]     = lo;   // coalesced: warp spans 32 consecutive c
    out[(r0 + 2 * p + 1) * CC + cg] = hi;
}

extern "C" void kernel_launch(void* const* d_in, const int* in_sizes, int n_in,
                              void* d_out, int out_size) {
    // Identify inputs by element count (robust to ordering):
    // x: 262144, w1: 256, w2: 4, w3: 32640, diff_indices: 8355840 (unused)
    const float* x = nullptr;
    const float* w1 = nullptr;
    const float* w2 = nullptr;
    const float* w3 = nullptr;
    for (int i = 0; i < n_in; i++) {
        switch (in_sizes[i]) {
            case BB * CC:            x  = (const float*)d_in[i]; break;
            case CC:                 w1 = (const float*)d_in[i]; break;
            case 4:                  w2 = (const float*)d_in[i]; break;
            case CC * (CC - 1) / 2:  w3 = (const float*)d_in[i]; break;
            default: break;  // diff_indices not needed
        }
    }

    build_W_kernel<<<(CC * CC + 255) / 256, 256>>>(w3);
    dim3 grid(CC / CTILE, BB / (2 * PAIRS));          // 8 x 64 = 512 blocks
    dim3 block(CTILE, PAIRS);                          // 256 threads
    son_main_kernel<<<grid, block>>>(x, w1, w2, (float*)d_out);
}